// round 1
// baseline (speedup 1.0000x reference)
#include <cuda_runtime.h>
#include <math.h>
#include <stdint.h>

// LSTM: T=1024, B=64, I=256, H=512, O=5
// out = [outputs (T*B*O) | h_T (B*H) | c_T (B*H)]  (pytree flatten order)

#define TT 1024
#define BB 64
#define II 256
#define HH 512
#define G4 2048
#define OO 5

#define REC_CTAS 128

// ---- device scratch (static __device__ globals: the sanctioned no-alloc path) ----
__device__ float g_xgT[(size_t)TT * G4 * BB];   // [T][4H][B]  pre-gates, 512MB
__device__ float g_hsT[(size_t)TT * HH * BB];   // [T][H][B]   h history, 128MB
__device__ float g_hT[2][HH * BB];              // ping-pong h, [512][64]
__device__ unsigned g_bar_count;
__device__ volatile unsigned g_bar_gen;

__device__ __forceinline__ float sigf(float x) {
    return 1.0f / (1.0f + __expf(-x));
}

// Hand-rolled grid barrier. Safe: all REC_CTAS CTAs are co-resident
// (128 CTAs <= 148 SMs, 1 CTA/SM at this smem/reg footprint).
// Self-resetting (count returns to 0 every barrier) -> graph-replay safe.
__device__ __forceinline__ void grid_sync() {
    __syncthreads();
    if (threadIdx.x == 0) {
        unsigned old = g_bar_gen;
        __threadfence();
        unsigned t = atomicAdd(&g_bar_count, 1u);
        if (t == REC_CTAS - 1) {
            atomicExch(&g_bar_count, 0u);
            __threadfence();
            g_bar_gen = old + 1u;
        } else {
            while (g_bar_gen == old) { }
            __threadfence();
        }
    }
    __syncthreads();
}

// ============================================================================
// Kernel 1: xg[t][n][b] = sum_k x[t][b][k] * W_ih[n][k] + b_ih[n] + b_hh[n]
// Tiled SGEMM: M-tile = 64 (one t), N-tile = 64, BK = 16, 256 threads, 4x4/thread.
// Output written TRANSPOSED per t ([4H][B]) so the recurrence reads coalesce.
// ============================================================================
__global__ void __launch_bounds__(256) pregemm_kernel(
    const float* __restrict__ x, const float* __restrict__ Wih,
    const float* __restrict__ bih, const float* __restrict__ bhh)
{
    __shared__ float As[16][68];   // [k][b]
    __shared__ float Bs[16][68];   // [k][n_local]
    const int t   = blockIdx.x >> 5;
    const int n0  = (blockIdx.x & 31) << 6;
    const int tid = threadIdx.x;
    const int lrow = tid >> 2;          // 0..63
    const int kk4  = (tid & 3) << 2;    // 0,4,8,12
    const int tx = tid & 15;            // n sub-tile
    const int ty = tid >> 4;            // b sub-tile

    const float* Ap = x   + (size_t)(t * BB) * II;
    const float* Bp = Wih + (size_t)n0 * II;

    float acc[4][4];
    #pragma unroll
    for (int i = 0; i < 4; i++)
        #pragma unroll
        for (int j = 0; j < 4; j++) acc[i][j] = 0.0f;

    for (int kc = 0; kc < II; kc += 16) {
        float4 a = *(const float4*)(Ap + (size_t)lrow * II + kc + kk4);
        float4 b = *(const float4*)(Bp + (size_t)lrow * II + kc + kk4);
        As[kk4+0][lrow] = a.x; As[kk4+1][lrow] = a.y;
        As[kk4+2][lrow] = a.z; As[kk4+3][lrow] = a.w;
        Bs[kk4+0][lrow] = b.x; Bs[kk4+1][lrow] = b.y;
        Bs[kk4+2][lrow] = b.z; Bs[kk4+3][lrow] = b.w;
        __syncthreads();
        #pragma unroll
        for (int kk = 0; kk < 16; kk++) {
            float4 av4 = *(const float4*)&As[kk][ty * 4];
            float4 bv4 = *(const float4*)&Bs[kk][tx * 4];
            float av[4] = {av4.x, av4.y, av4.z, av4.w};
            float bv[4] = {bv4.x, bv4.y, bv4.z, bv4.w};
            #pragma unroll
            for (int i = 0; i < 4; i++)
                #pragma unroll
                for (int jj = 0; jj < 4; jj++)
                    acc[i][jj] = fmaf(av[i], bv[jj], acc[i][jj]);
        }
        __syncthreads();
    }

    float* outp = g_xgT + (size_t)t * (G4 * BB);
    #pragma unroll
    for (int jj = 0; jj < 4; jj++) {
        int n = n0 + tx * 4 + jj;
        float bias = bih[n] + bhh[n];
        float4 v = make_float4(acc[0][jj] + bias, acc[1][jj] + bias,
                               acc[2][jj] + bias, acc[3][jj] + bias);
        *(float4*)(outp + (size_t)n * BB + ty * 4) = v;
    }
}

// ============================================================================
// Kernel 2: persistent LSTM recurrence. 128 CTAs x 256 threads.
// CTA j owns hidden units [4j, 4j+4) -> 16 gate rows {i,f,g,o} x 4 units.
// W_hh slice (16x512) + cell state live in SMEM across all 1024 steps.
// Per step: 64x16 GEMM slice vs full h (K=512), nonlinearity, h broadcast,
// grid barrier.
// ============================================================================
__global__ void __launch_bounds__(256, 1) lstm_rec_kernel(
    const float* __restrict__ Whh, float* __restrict__ d_out, int out_size)
{
    __shared__ float wsm[16][516];   // padded: 516 % 32 = 4 -> no LDS conflict
    __shared__ float gsm[16][64];    // gate pre-activations for this step
    __shared__ float csm[4][64];     // cell state (persistent across steps)

    const int j   = blockIdx.x;
    const int tid = threadIdx.x;
    const int bq  = tid & 15;        // batch quad: b = 4*bq .. 4*bq+3
    const int rid = tid >> 4;        // 0..15: local gate row
    const int gate = rid >> 2;
    const int u    = rid & 3;
    const int grow = gate * HH + j * 4 + u;   // global gate row in [0,2048)

    // Load W_hh rows for this CTA (coalesced over k)
    for (int s = tid; s < 16 * HH; s += 256) {
        int r = s >> 9;
        int k = s & (HH - 1);
        int rr = (r >> 2) * HH + j * 4 + (r & 3);
        wsm[r][k] = Whh[(size_t)rr * HH + k];
    }
    // Zero cell state and this CTA's slice of h0 (per-replay reset)
    {
        int uu = tid >> 6, b = tid & 63;
        csm[uu][b] = 0.0f;
        g_hT[0][(j * 4 + uu) * BB + b] = 0.0f;
    }
    __threadfence();
    grid_sync();

    int cur = 0;
    for (int step = 0; step < TT; step++) {
        // init accumulators from precomputed x-gates (already include biases)
        const float* xgp = g_xgT + (size_t)step * (G4 * BB)
                                 + (size_t)grow * BB + bq * 4;
        float4 acc = *(const float4*)xgp;

        // gates[b, grow] += sum_k h[k][b] * W_hh[grow][k]
        const float4* hp = (const float4*)(g_hT[cur]) + bq;  // + k*16 per step
        #pragma unroll 8
        for (int k = 0; k < HH; k++) {
            float4 hv = __ldcg(hp + k * 16);   // L2 (h written by other SMs)
            float w = wsm[rid][k];
            acc.x = fmaf(hv.x, w, acc.x);
            acc.y = fmaf(hv.y, w, acc.y);
            acc.z = fmaf(hv.z, w, acc.z);
            acc.w = fmaf(hv.w, w, acc.w);
        }
        gsm[rid][bq * 4 + 0] = acc.x;
        gsm[rid][bq * 4 + 1] = acc.y;
        gsm[rid][bq * 4 + 2] = acc.z;
        gsm[rid][bq * 4 + 3] = acc.w;
        __syncthreads();

        // elementwise LSTM cell: thread -> (unit uu, batch b)
        {
            int uu = tid >> 6, b = tid & 63;
            float ig = sigf(gsm[uu][b]);
            float fg = sigf(gsm[4 + uu][b]);
            float gg = tanhf(gsm[8 + uu][b]);
            float og = sigf(gsm[12 + uu][b]);
            float c  = fmaf(fg, csm[uu][b], ig * gg);
            float h  = og * tanhf(c);
            csm[uu][b] = c;
            int gu = j * 4 + uu;
            g_hT[cur ^ 1][gu * BB + b] = h;                          // broadcast
            g_hsT[(size_t)step * (HH * BB) + gu * BB + b] = h;       // history
            if (step == TT - 1 && out_size >= TT * BB * OO + 2 * BB * HH) {
                d_out[TT * BB * OO + (size_t)b * HH + gu] = h;           // h_T
                d_out[TT * BB * OO + BB * HH + (size_t)b * HH + gu] = c; // c_T
            }
        }
        __threadfence();
        grid_sync();
        cur ^= 1;
    }
}

// ============================================================================
// Kernel 3: outputs[t][b][o] = sum_k hsT[t][k][b] * fc_w[o][k] + fc_b[o]
// One CTA per t; 320 threads = 5 o-groups x 64 b. Memory-bound over 128MB.
// ============================================================================
__global__ void __launch_bounds__(320) fc_kernel(
    const float* __restrict__ fcw, const float* __restrict__ fcb,
    float* __restrict__ out)
{
    __shared__ float wsm[OO][HH];
    __shared__ float bsm[OO];
    const int t   = blockIdx.x;
    const int tid = threadIdx.x;
    for (int s = tid; s < OO * HH; s += 320) wsm[s / HH][s % HH] = fcw[s];
    if (tid < OO) bsm[tid] = fcb[tid];
    __syncthreads();

    const int o = tid >> 6;   // 0..4
    const int b = tid & 63;
    const float* hp = g_hsT + (size_t)t * (HH * BB) + b;
    float acc = bsm[o];
    #pragma unroll 8
    for (int k = 0; k < HH; k++)
        acc = fmaf(hp[(size_t)k * BB], wsm[o][k], acc);
    out[(size_t)t * (BB * OO) + b * OO + o] = acc;
}

// ============================================================================
extern "C" void kernel_launch(void* const* d_in, const int* in_sizes, int n_in,
                              void* d_out, int out_size) {
    const float* x   = (const float*)d_in[0];   // [T,B,I]
    const float* Wih = (const float*)d_in[1];   // [4H,I]
    const float* Whh = (const float*)d_in[2];   // [4H,H]
    const float* bih = (const float*)d_in[3];   // [4H]
    const float* bhh = (const float*)d_in[4];   // [4H]
    const float* fcw = (const float*)d_in[5];   // [O,H]
    const float* fcb = (const float*)d_in[6];   // [O]
    float* out = (float*)d_out;

    pregemm_kernel<<<TT * 32, 256>>>(x, Wih, bih, bhh);
    lstm_rec_kernel<<<REC_CTAS, 256>>>(Whh, out, out_size);
    fc_kernel<<<TT, 320>>>(fcw, fcb, out);
}